// round 7
// baseline (speedup 1.0000x reference)
#include <cuda_runtime.h>
#include <cstdint>

// ----------------------------------------------------------------------------
// BaseLUTLayer = multilinear polynomial eval in Moebius coefficient basis.
//   prep_kernel:  (a) transpose x -> xT[IN][B], 64x64 float4 tiles
//                 (b) Moebius transform lut -> C
//   lut_fold_kernel: nested Horner, f32x2 over batch, BPT=2, 4 chunks/block,
//     software-pipelined X prefetch (chunk c+1 loaded before computing c),
//     register-lean fused bit0+1 stream. Double-buffered staging writeout.
// ----------------------------------------------------------------------------

#define O_TILE  8
#define BPT     2
#define B_TILE  (32 * BPT * 2)   // 128 b per chunk (lane covers 2, two... see map)
#define CHUNKS  4

// NOTE: with BPT=2 a warp covers 64 b per chunk; we keep 128-b chunks by
// giving each warp TWO adjacent 64-b half-chunks? Simpler: chunk = 64 b.
// Redefine: chunk = 64 b, 16 chunks over B=1024, grid.x = B/(64*CHUNKS_TOT).
#undef B_TILE
#define B_CHUNK 64               // b per chunk (32 lanes x BPT=2)
#define N_CHUNK 4                // chunks per block

__device__ float g_xT[4 * 1024 * 1024];
__device__ float g_C [1 * 1024 * 1024];

static __device__ __forceinline__ unsigned long long pack2(float lo, float hi) {
    unsigned long long r;
    asm("mov.b64 %0, {%1, %2};" : "=l"(r) : "f"(lo), "f"(hi));
    return r;
}
static __device__ __forceinline__ void unpack2(unsigned long long v, float& lo, float& hi) {
    asm("mov.b64 {%0, %1}, %2;" : "=f"(lo), "=f"(hi) : "l"(v));
}
static __device__ __forceinline__ unsigned long long fma2(unsigned long long a,
                                                          unsigned long long b,
                                                          unsigned long long c) {
    unsigned long long d;
    asm("fma.rn.f32x2 %0, %1, %2, %3;" : "=l"(d) : "l"(a), "l"(b), "l"(c));
    return d;
}

// ---- fused prep: transpose (first t_blocks) + Moebius coeffs (rest) --------
__global__ __launch_bounds__(256)
void prep_kernel(const float* __restrict__ x, float* __restrict__ xT,
                 const float* __restrict__ lut, float* __restrict__ C,
                 int B, int IN, int OUT, int t_blocks, int tiles_x) {
    if ((int)blockIdx.x < t_blocks) {
        __shared__ float tile[64][65];
        const int tid = threadIdx.x;
        const int c0 = (blockIdx.x % tiles_x) * 64;    // IN base
        const int r0 = (blockIdx.x / tiles_x) * 64;    // B base
        float4 v[4];
#pragma unroll
        for (int p = 0; p < 4; p++) {
            int idx  = p * 256 + tid;
            int row  = idx >> 4;
            int col4 = idx & 15;
            int r = r0 + row, c = c0 + col4 * 4;
            v[p] = (r < B && c + 3 < IN)
                 ? *reinterpret_cast<const float4*>(&x[(size_t)r * IN + c])
                 : make_float4(0.f, 0.f, 0.f, 0.f);
        }
#pragma unroll
        for (int p = 0; p < 4; p++) {
            int idx  = p * 256 + tid;
            int row  = idx >> 4;
            int col4 = idx & 15;
            tile[row][col4 * 4 + 0] = v[p].x;
            tile[row][col4 * 4 + 1] = v[p].y;
            tile[row][col4 * 4 + 2] = v[p].z;
            tile[row][col4 * 4 + 3] = v[p].w;
        }
        __syncthreads();
#pragma unroll
        for (int p = 0; p < 4; p++) {
            int idx = p * 256 + tid;
            int inl = idx >> 4;
            int b4  = idx & 15;
            int in = c0 + inl, bb = r0 + b4 * 4;
            if (in < IN && bb + 3 < B) {
                float4 w = make_float4(tile[b4 * 4 + 0][inl],
                                       tile[b4 * 4 + 1][inl],
                                       tile[b4 * 4 + 2][inl],
                                       tile[b4 * 4 + 3][inl]);
                *reinterpret_cast<float4*>(&xT[(size_t)in * B + bb]) = w;
            }
        }
    } else {
        int o = (blockIdx.x - t_blocks) * 256 + threadIdx.x;
        if (o >= OUT) return;
        float a[64];
        const float4* src = reinterpret_cast<const float4*>(lut + (size_t)o * 64);
#pragma unroll
        for (int i = 0; i < 16; i++) {
            float4 w = __ldg(&src[i]);
            a[4 * i] = w.x; a[4 * i + 1] = w.y; a[4 * i + 2] = w.z; a[4 * i + 3] = w.w;
        }
#pragma unroll
        for (int j = 0; j < 6; j++) {
            int s = 1 << j;
#pragma unroll
            for (int k = 0; k < 64; k++)
                if (k & s) a[k] -= a[k ^ s];
        }
        float4* dst = reinterpret_cast<float4*>(C + (size_t)o * 64);
#pragma unroll
        for (int i = 0; i < 16; i++)
            dst[i] = make_float4(a[4 * i], a[4 * i + 1], a[4 * i + 2], a[4 * i + 3]);
    }
}

// ---- fold: BPT=2, prefetched chunk loop, lean Horner -----------------------
__global__ __launch_bounds__(256, 4)
void lut_fold_kernel(const float* __restrict__ xT,
                     const float* __restrict__ C,
                     const int*   __restrict__ mapping,
                     float* __restrict__ out,
                     int B, int OUT) {
    __shared__ ulonglong2 s_lut[O_TILE][32];
    __shared__ float      s_res[2][O_TILE][B_CHUNK + 4];

    const int lane = threadIdx.x;
    const int ty   = threadIdx.y;
    const int tid  = ty * 32 + lane;
    const int b00  = blockIdx.x * (B_CHUNK * N_CHUNK);
    const int o0   = blockIdx.y * O_TILE;
    int o = o0 + ty;
    if (o >= OUT) o = OUT - 1;

    // per-warp prologue
    float2 cpair = *reinterpret_cast<const float2*>(&C[(size_t)o * 64 + 2 * lane]);
    int m[6];
#pragma unroll
    for (int j = 0; j < 6; j++) m[j] = __ldg(&mapping[(size_t)o * 6 + j]);
    {
        ulonglong2 e;
        e.x = pack2(cpair.x, cpair.x);
        e.y = pack2(cpair.y, cpair.y);
        s_lut[ty][lane] = e;
    }
    __syncwarp();

    const ulonglong2* lrow = &s_lut[ty][0];
    const int bl = lane * BPT;   // lane's offset within a chunk

    // prefetch chunk 0
    unsigned long long Xn[6];
    {
        const int bq = b00 + bl;
        const bool vb = (bq + 1 < B);
#pragma unroll
        for (int j = 0; j < 6; j++)
            Xn[j] = vb ? *reinterpret_cast<const unsigned long long*>(&xT[(size_t)m[j] * B + bq])
                       : 0ull;
    }

#pragma unroll
    for (int c = 0; c < N_CHUNK; c++) {
        unsigned long long X[6];
#pragma unroll
        for (int j = 0; j < 6; j++) X[j] = Xn[j];

        if (c + 1 < N_CHUNK) {               // prefetch next chunk's x
            const int bq = b00 + (c + 1) * B_CHUNK + bl;
            const bool vb = (bq + 1 < B);
#pragma unroll
            for (int j = 0; j < 6; j++)
                Xn[j] = vb ? *reinterpret_cast<const unsigned long long*>(&xT[(size_t)m[j] * B + bq])
                           : 0ull;
        }

        // lean Horner: fused bit0+bit1 stream, progressive bit4/5 accumulation
        unsigned long long acc0, acc1;
#pragma unroll
        for (int g = 0; g < 4; g++) {
            unsigned long long w[4];
#pragma unroll
            for (int i = 0; i < 4; i++) {
                ulonglong2 e0 = lrow[g * 8 + 2 * i];
                ulonglong2 e1 = lrow[g * 8 + 2 * i + 1];
                unsigned long long ta = fma2(X[0], e0.y, e0.x);  // bit 0
                unsigned long long tb = fma2(X[0], e1.y, e1.x);
                w[i] = fma2(X[1], tb, ta);                       // bit 1
            }
            unsigned long long u0 = fma2(X[2], w[1], w[0]);      // bit 2
            unsigned long long u1 = fma2(X[2], w[3], w[2]);
            unsigned long long rg = fma2(X[3], u1, u0);          // bit 3
            if (g == 0)      acc0 = rg;
            else if (g == 1) acc0 = fma2(X[4], rg, acc0);        // bit 4
            else if (g == 2) acc1 = rg;
            else             acc1 = fma2(X[4], rg, acc1);
        }
        unsigned long long res = fma2(X[5], acc1, acc0);         // bit 5

        float r0f, r1f;
        unpack2(res, r0f, r1f);
        *reinterpret_cast<float2*>(&s_res[c & 1][ty][bl]) = make_float2(r0f, r1f);
        __syncthreads();

        // writeout: 256 threads cover 64 b x 8 o as float4 (o fastest)
        int bw   = tid >> 2;                 // 0..63
        int half = tid & 1;                  // low bit -> o group
        int rep  = (tid >> 1) & 1;           // duplicate work guard
        int oo   = o0 + half * 4;
        int bg   = b00 + c * B_CHUNK + bw;
        if (rep == 0 && bg < B && oo + 3 < OUT) {
            float4 val = make_float4(s_res[c & 1][half * 4 + 0][bw],
                                     s_res[c & 1][half * 4 + 1][bw],
                                     s_res[c & 1][half * 4 + 2][bw],
                                     s_res[c & 1][half * 4 + 3][bw]);
            *reinterpret_cast<float4*>(&out[(size_t)bg * OUT + oo]) = val;
        }
    }
}

extern "C" void kernel_launch(void* const* d_in, const int* in_sizes, int n_in,
                              void* d_out, int out_size) {
    const float* x       = (const float*)d_in[0];
    const float* lut     = (const float*)d_in[1];
    const int*   mapping = (const int*)d_in[2];
    float*       out     = (float*)d_out;

    int OUT = in_sizes[2] / 6;          // mapping is (OUT, 6)
    int B   = out_size / OUT;           // out is (B, OUT)
    int IN  = in_sizes[0] / B;          // x is (B, IN)

    float* xT = nullptr;
    float* C  = nullptr;
    cudaGetSymbolAddress((void**)&xT, g_xT);
    cudaGetSymbolAddress((void**)&C,  g_C);

    int tiles_x  = (IN + 63) / 64;
    int tiles_y  = (B + 63) / 64;
    int t_blocks = tiles_x * tiles_y;
    int c_blocks = (OUT + 255) / 256;
    prep_kernel<<<t_blocks + c_blocks, 256>>>(x, xT, lut, C, B, IN, OUT, t_blocks, tiles_x);

    dim3 blk(32, O_TILE);
    dim3 grd((B + B_CHUNK * N_CHUNK - 1) / (B_CHUNK * N_CHUNK),
             (OUT + O_TILE - 1) / O_TILE);
    lut_fold_kernel<<<grd, blk>>>(xT, C, mapping, out, B, OUT);
}